// round 7
// baseline (speedup 1.0000x reference)
#include <cuda_runtime.h>
#include <math.h>
#include <stdint.h>

#define NB 8
#define NT 1024
#define ND 512
#define NH 8
#define NDK 64
#define NTOK (NB*NT)

// ---------------- scratch (no allocation allowed) ----------------
static __device__ float g_normed[NTOK*ND];
static __device__ float g_qb[NTOK*ND];
static __device__ float g_kb[NTOK*ND];
static __device__ float g_vb[NTOK*ND];       // V stored [b,h,dk,t] for flash
static __device__ float g_attnb[NTOK*ND];
static __device__ float g_h1[NTOK*ND];
static __device__ float g_wt[8*ND*ND];       // transposed tf32-rounded weights [n][k]
static __device__ float g_ctab[32*NT];
static __device__ float g_stab[32*NT];

// ---------------- PTX helpers (all plain sm_80 features, OK for .target sm_103) --
__device__ __forceinline__ float tf32r(float x) {
    uint32_t u = __float_as_uint(x), o;
    asm("cvt.rna.tf32.f32 %0, %1;" : "=r"(o) : "r"(u));
    return __uint_as_float(o);
}
__device__ __forceinline__ void mma_tf32(float* c, const uint32_t* a, const uint32_t* b) {
    asm volatile("mma.sync.aligned.m16n8k8.row.col.f32.tf32.tf32.f32 "
        "{%0,%1,%2,%3}, {%4,%5,%6,%7}, {%8,%9}, {%0,%1,%2,%3};"
        : "+f"(c[0]), "+f"(c[1]), "+f"(c[2]), "+f"(c[3])
        : "r"(a[0]), "r"(a[1]), "r"(a[2]), "r"(a[3]), "r"(b[0]), "r"(b[1]));
}
__device__ __forceinline__ uint32_t smem_u32(const void* p) {
    uint32_t a;
    asm("{ .reg .u64 t; cvta.to.shared.u64 t, %1; cvt.u32.u64 %0, t; }" : "=r"(a) : "l"(p));
    return a;
}
#define CP_ASYNC16(dst, src) \
    asm volatile("cp.async.cg.shared.global [%0], [%1], 16;" :: "r"(dst), "l"(src))
#define CP_COMMIT() asm volatile("cp.async.commit_group;")
#define CP_WAIT(n)  asm volatile("cp.async.wait_group %0;" :: "n"(n))
#define LDSM_X4(r, addr) \
    asm volatile("ldmatrix.sync.aligned.m8n8.x4.shared.b16 {%0,%1,%2,%3}, [%4];" \
        : "=r"((r)[0]), "=r"((r)[1]), "=r"((r)[2]), "=r"((r)[3]) : "r"(addr))

// old float-index swizzle (flash kernel only)
__device__ __forceinline__ int swz(int row, int k) {
    int g = ((k & 3) << 1) | ((k >> 4) & 1);
    return row * 32 + (((g ^ (row & 7)) << 2) | ((k >> 2) & 3));
}

// ---------------- weight transpose + tf32 rounding ----------------
struct WPtrs { const float* p[8]; };
__global__ void __launch_bounds__(256) transpose_w(WPtrs ws, float* wt) {
    __shared__ float tile[32][33];
    const float* W = ws.p[blockIdx.z];
    float* O = wt + (size_t)blockIdx.z * (ND*ND);
    int n = blockIdx.x * 32 + threadIdx.x;
    int k0 = blockIdx.y * 32;
    for (int i = threadIdx.y; i < 32; i += 8)
        tile[i][threadIdx.x] = W[(size_t)(k0 + i) * ND + n];
    __syncthreads();
    int k = k0 + threadIdx.x;
    int nb = blockIdx.x * 32;
    for (int i = threadIdx.y; i < 32; i += 8)
        O[(size_t)(nb + i) * ND + k] = tf32r(tile[threadIdx.x][i]);
}

// ---------------- rope tables ----------------
__global__ void rope_table_k(float* ct, float* st) {
    int t = blockIdx.x * 128 + threadIdx.x;
#pragma unroll
    for (int j = 0; j < 32; j++) {
        float inv = exp2f(-((float)(2 * j) * (1.0f/NDK)) * 13.287712379549449f);
        float sn, cs;
        sincosf((float)t * inv, &sn, &cs);
        ct[j * NT + t] = cs;
        st[j * NT + t] = sn;
    }
}

// ---------------- RMSNorm (tf32-rounded output: feeds GEMM A via cp.async) ----
__global__ void __launch_bounds__(128) rmsnorm_kernel(
    const float* __restrict__ x, const float* __restrict__ w, float* __restrict__ out)
{
    int token = blockIdx.x;
    int tid = threadIdx.x;
    const float4 v = reinterpret_cast<const float4*>(x + (size_t)token*ND)[tid];
    float ss = v.x*v.x + v.y*v.y + v.z*v.z + v.w*v.w;
#pragma unroll
    for (int off = 16; off; off >>= 1) ss += __shfl_xor_sync(0xffffffffu, ss, off);
    __shared__ float red[4];
    if ((tid & 31) == 0) red[tid >> 5] = ss;
    __syncthreads();
    float tot = red[0] + red[1] + red[2] + red[3];
    float r = rsqrtf(tot * (1.0f/ND) + 1e-6f);
    const float4 wv = reinterpret_cast<const float4*>(w)[tid];
    float4 o;
    o.x = tf32r(v.x*r*wv.x); o.y = tf32r(v.y*r*wv.y);
    o.z = tf32r(v.z*r*wv.z); o.w = tf32r(v.w*r*wv.w);
    reinterpret_cast<float4*>(out + (size_t)token*ND)[tid] = o;
}

// ======================= cp.async + ldmatrix tf32 GEMM =======================
// CTA tile 128x128, BK=32, 3-stage cp.async pipeline, 8 warps (2x4), warp 64x32.
// SMEM 16B-group layout: slot(row, gb) = row*128B + ((gb ^ (row&7))*16B).
// MODE 0: C+R -> o0 flat [token,512]         (grid 4 x 64)
// MODE 1: fused QKV time: w0->rope q, w1->rope k, w2->v [b,h,dk,t]  (grid 12 x 64)
// MODE 2: fused QKV group: flat writes to o0/o1/o2                  (grid 12 x 64)
#define GSMEM_BYTES 98304   // 3 stages x (16KB A + 16KB B)

template<int MODE>
__global__ void __launch_bounds__(256, 2) gemm_f(
    const float* __restrict__ A, const float* __restrict__ Bt,
    const float* __restrict__ R,
    float* __restrict__ o0, float* __restrict__ o1, float* __restrict__ o2,
    const float* __restrict__ ctab, const float* __restrict__ stab)
{
    extern __shared__ float sm[];
    const int tid = threadIdx.x;
    const int wid = tid >> 5, lane = tid & 31;
    const int warp_m = wid >> 2, warp_n = wid & 3;
    const int r = lane >> 2, q = lane & 3;
    const int m0 = blockIdx.y * 128;
    const int n0 = blockIdx.x * 128;

    const float* Ap = A + (size_t)m0 * ND;
    const float* Bp = Bt + (size_t)n0 * ND;
    const uint32_t sbase = smem_u32(sm);

    // per-thread cp.async source/dest pattern
    const int crow = tid >> 3, cgb = tid & 7;

    float acc[4][4][4];
#pragma unroll
    for (int mt = 0; mt < 4; mt++)
#pragma unroll
        for (int nt = 0; nt < 4; nt++)
#pragma unroll
            for (int i = 0; i < 4; i++) acc[mt][nt][i] = 0.f;

    // ---- prologue: stages 0,1,2 ----
#pragma unroll
    for (int s = 0; s < 3; s++) {
        uint32_t sa = sbase + s * 32768, sb = sa + 16384;
        int kc = s * 32;
#pragma unroll
        for (int u = 0; u < 4; u++) {
            int rr = crow + u*32;
            uint32_t off = (uint32_t)(rr*128 + ((cgb ^ (rr & 7)) << 4));
            CP_ASYNC16(sa + off, Ap + (size_t)rr*ND + kc + cgb*4);
            CP_ASYNC16(sb + off, Bp + (size_t)rr*ND + kc + cgb*4);
        }
        CP_COMMIT();
    }

    const int mi = lane >> 3, mrow = lane & 7;

    for (int kt = 0; kt < 16; kt++) {
        if (kt <= 13)      CP_WAIT(2);
        else if (kt == 14) CP_WAIT(1);
        else               CP_WAIT(0);
        __syncthreads();

        uint32_t stA = sbase + (kt % 3) * 32768;
        uint32_t stB = stA + 16384;

#pragma unroll
        for (int kb = 0; kb < 4; kb++) {
            uint32_t a[4][4], bq[2][4];
#pragma unroll
            for (int mt = 0; mt < 4; mt++) {
                int row = warp_m*64 + mt*16 + (mi & 1)*8 + mrow;
                int gb = 2*kb + (mi >> 1);
                LDSM_X4(a[mt], stA + row*128 + ((gb ^ (row & 7)) << 4));
            }
#pragma unroll
            for (int np = 0; np < 2; np++) {
                int row = warp_n*32 + (2*np + (mi >> 1))*8 + mrow;
                int gb = 2*kb + (mi & 1);
                LDSM_X4(bq[np], stB + row*128 + ((gb ^ (row & 7)) << 4));
            }
#pragma unroll
            for (int mt = 0; mt < 4; mt++)
#pragma unroll
                for (int nt = 0; nt < 4; nt++)
                    mma_tf32(acc[mt][nt], a[mt], &bq[nt >> 1][(nt & 1) * 2]);
        }
        __syncthreads();

        if (kt + 3 < 16) {
            int s = (kt + 3) % 3, kc = (kt + 3) * 32;
            uint32_t sa = sbase + s * 32768, sb = sa + 16384;
#pragma unroll
            for (int u = 0; u < 4; u++) {
                int rr = crow + u*32;
                uint32_t off = (uint32_t)(rr*128 + ((cgb ^ (rr & 7)) << 4));
                CP_ASYNC16(sa + off, Ap + (size_t)rr*ND + kc + cgb*4);
                CP_ASYNC16(sb + off, Bp + (size_t)rr*ND + kc + cgb*4);
            }
            CP_COMMIT();
        }
    }

    // ---- epilogue: stage C in SMEM ----
    float* Cs = sm;
#pragma unroll
    for (int mt = 0; mt < 4; mt++)
#pragma unroll
        for (int nt = 0; nt < 4; nt++) {
            int rb = warp_m*64 + mt*16 + r;
            int cb = warp_n*32 + nt*8 + 2*q;
            Cs[rb*132 + cb]         = acc[mt][nt][0];
            Cs[rb*132 + cb + 1]     = acc[mt][nt][1];
            Cs[(rb+8)*132 + cb]     = acc[mt][nt][2];
            Cs[(rb+8)*132 + cb + 1] = acc[mt][nt][3];
        }
    __syncthreads();

    const int row = tid & 127, hc = tid >> 7;
    const int grow = m0 + row;
    const int bb = grow >> 10, t = grow & (NT - 1);
    const float* cr = Cs + row*132 + hc*64;

    if (MODE == 0) {
        size_t base = (size_t)grow * ND + n0 + hc*64;
#pragma unroll
        for (int v = 0; v < 16; v++) {
            float4 x = *reinterpret_cast<const float4*>(cr + 4*v);
            float4 r4 = *reinterpret_cast<const float4*>(R + base + 4*v);
            x.x += r4.x; x.y += r4.y; x.z += r4.z; x.w += r4.w;
            *reinterpret_cast<float4*>(o0 + base + 4*v) = x;
        }
    } else if (MODE == 1) {
        int w = blockIdx.x >> 2;
        int head = (blockIdx.x & 3)*2 + hc;
        if (w < 2) {   // rope -> q or k, [b,h,t,dk]
            float* o = (w == 0) ? o0 : o1;
            size_t obase = ((size_t)(bb*NH + head)*NT + t)*NDK;
            float lo[32], hi[32];
#pragma unroll
            for (int j = 0; j < 32; j++) {
                float cs = ctab[j*NT + t], sn = stab[j*NT + t];
                float l0 = cr[j], h0 = cr[j + 32];
                lo[j] = l0*cs - h0*sn;
                hi[j] = h0*cs + l0*sn;
            }
#pragma unroll
            for (int v = 0; v < 8; v++) {
                *reinterpret_cast<float4*>(o + obase + 4*v)      = *reinterpret_cast<float4*>(lo + 4*v);
                *reinterpret_cast<float4*>(o + obase + 32 + 4*v) = *reinterpret_cast<float4*>(hi + 4*v);
            }
        } else {       // v -> [b,h,dk,t]
            size_t obase = ((size_t)(bb*NH + head)*NDK)*NT + t;
#pragma unroll
            for (int j = 0; j < 64; j++)
                o2[obase + (size_t)j*NT] = cr[j];
        }
    } else {           // MODE 2: flat q/k/v for group attention
        int w = blockIdx.x >> 2;
        float* o = (w == 0) ? o0 : (w == 1) ? o1 : o2;
        size_t base = (size_t)grow * ND + (blockIdx.x & 3)*128 + hc*64;
#pragma unroll
        for (int v = 0; v < 16; v++)
            *reinterpret_cast<float4*>(o + base + 4*v) =
                *reinterpret_cast<const float4*>(cr + 4*v);
    }
}

// ======================= Flash attention via mma.sync tf32 (as R6, +rounded out) ==
#define FL_SMEM_FLOATS 16384

__global__ void __launch_bounds__(256) flash_mma(
    const float* __restrict__ Q, const float* __restrict__ K,
    const float* __restrict__ Vt, float* __restrict__ out)
{
    extern __shared__ float sm[];
    float* QP = sm;
    float* Ks = sm + 8192;
    float* Vs = sm + 12288;
    const int tid = threadIdx.x, wid = tid >> 5, lane = tid & 31;
    const int r = lane >> 2, q = lane & 3;
    const int qt = blockIdx.x, bh = blockIdx.y;
    const float* qp = Q  + ((size_t)bh*NT + qt*128)*NDK;
    const float* kp = K  + (size_t)bh*NT*NDK;
    const float* vp = Vt + (size_t)bh*NDK*NT;

#pragma unroll
    for (int u = 0; u < 8; u++) {
        int gi = tid + u*256;
        int row = gi >> 4, d0 = (gi & 15) * 4;
        float4 v4 = *reinterpret_cast<const float4*>(qp + (size_t)row*NDK + d0);
        float* dst = QP + (d0 >> 5) * 4096;
        int kk = d0 & 31;
        dst[swz(row, kk+0)] = tf32r(v4.x * 0.125f);
        dst[swz(row, kk+1)] = tf32r(v4.y * 0.125f);
        dst[swz(row, kk+2)] = tf32r(v4.z * 0.125f);
        dst[swz(row, kk+3)] = tf32r(v4.w * 0.125f);
    }
    __syncthreads();

    uint32_t aq[2][2][2][4];
#pragma unroll
    for (int kc = 0; kc < 2; kc++)
#pragma unroll
        for (int h = 0; h < 2; h++)
#pragma unroll
            for (int rr = 0; rr < 2; rr++) {
                int row = wid*16 + r + rr*8;
                uint4 v4 = *reinterpret_cast<const uint4*>(
                    QP + kc*4096 + row*32 + ((((q<<1)|h) ^ (row & 7)) << 2));
                aq[kc][h][rr][0]=v4.x; aq[kc][h][rr][1]=v4.y;
                aq[kc][h][rr][2]=v4.z; aq[kc][h][rr][3]=v4.w;
            }
    __syncthreads();

    float4 kr[4], vr[4];
#pragma unroll
    for (int u = 0; u < 4; u++) {
        int gi = tid + u*256;
        int row = gi >> 4, c4 = (gi & 15) * 4;
        kr[u] = *reinterpret_cast<const float4*>(kp + (size_t)row*NDK + c4);
        vr[u] = *reinterpret_cast<const float4*>(vp + (size_t)row*NT + c4);
    }

    float m_[2] = {-1e30f, -1e30f}, l_[2] = {0.f, 0.f};
    float oacc[8][4];
#pragma unroll
    for (int nt = 0; nt < 8; nt++)
#pragma unroll
        for (int i = 0; i < 4; i++) oacc[nt][i] = 0.f;

    for (int kt = 0; kt < 16; kt++) {
#pragma unroll
        for (int u = 0; u < 4; u++) {
            int gi = tid + u*256;
            int row = gi >> 4, c4 = (gi & 15) * 4;
            {
                float* dst = Ks + (c4 >> 5) * 2048;
                int kk = c4 & 31;
                dst[swz(row, kk+0)] = tf32r(kr[u].x);
                dst[swz(row, kk+1)] = tf32r(kr[u].y);
                dst[swz(row, kk+2)] = tf32r(kr[u].z);
                dst[swz(row, kk+3)] = tf32r(kr[u].w);
            }
            {
                float* dst = Vs + (c4 >> 5) * 2048;
                int kk = c4 & 31;
                dst[swz(row, kk+0)] = tf32r(vr[u].x);
                dst[swz(row, kk+1)] = tf32r(vr[u].y);
                dst[swz(row, kk+2)] = tf32r(vr[u].z);
                dst[swz(row, kk+3)] = tf32r(vr[u].w);
            }
        }
        __syncthreads();

        float sacc[8][4];
#pragma unroll
        for (int nt = 0; nt < 8; nt++)
#pragma unroll
            for (int i = 0; i < 4; i++) sacc[nt][i] = 0.f;
#pragma unroll
        for (int kc = 0; kc < 2; kc++)
#pragma unroll
            for (int h = 0; h < 2; h++) {
                const float* sB = Ks + kc*2048;
#pragma unroll
                for (int sh = 0; sh < 2; sh++) {
                    int e = sh*2;
                    uint32_t a[4] = { aq[kc][h][0][e], aq[kc][h][1][e],
                                      aq[kc][h][0][e+1], aq[kc][h][1][e+1] };
#pragma unroll
                    for (int nt = 0; nt < 8; nt++) {
                        int row = nt*8 + r;
                        uint2 bv = *reinterpret_cast<const uint2*>(
                            sB + row*32 + ((((q<<1)|h) ^ (row & 7)) << 2) + e);
                        uint32_t b[2] = { bv.x, bv.y };
                        mma_tf32(sacc[nt], a, b);
                    }
                }
            }

        if (kt < 15) {
            const float* kpn = kp + (size_t)(kt+1)*64*NDK;
            const float* vpn = vp + (kt+1)*64;
#pragma unroll
            for (int u = 0; u < 4; u++) {
                int gi = tid + u*256;
                int row = gi >> 4, c4 = (gi & 15) * 4;
                kr[u] = *reinterpret_cast<const float4*>(kpn + (size_t)row*NDK + c4);
                vr[u] = *reinterpret_cast<const float4*>(vpn + (size_t)row*NT + c4);
            }
        }

        float tmax0 = -1e30f, tmax1 = -1e30f;
#pragma unroll
        for (int nt = 0; nt < 8; nt++) {
            tmax0 = fmaxf(tmax0, fmaxf(sacc[nt][0], sacc[nt][1]));
            tmax1 = fmaxf(tmax1, fmaxf(sacc[nt][2], sacc[nt][3]));
        }
        tmax0 = fmaxf(tmax0, __shfl_xor_sync(0xffffffffu, tmax0, 1));
        tmax0 = fmaxf(tmax0, __shfl_xor_sync(0xffffffffu, tmax0, 2));
        tmax1 = fmaxf(tmax1, __shfl_xor_sync(0xffffffffu, tmax1, 1));
        tmax1 = fmaxf(tmax1, __shfl_xor_sync(0xffffffffu, tmax1, 2));
        float mn0 = fmaxf(m_[0], tmax0), mn1 = fmaxf(m_[1], tmax1);
        float cr0 = __expf(m_[0] - mn0), cr1 = __expf(m_[1] - mn1);
        m_[0] = mn0; m_[1] = mn1;
        float rs0 = 0.f, rs1 = 0.f;
#pragma unroll
        for (int nt = 0; nt < 8; nt++) {
            sacc[nt][0] = __expf(sacc[nt][0] - mn0); rs0 += sacc[nt][0];
            sacc[nt][1] = __expf(sacc[nt][1] - mn0); rs0 += sacc[nt][1];
            sacc[nt][2] = __expf(sacc[nt][2] - mn1); rs1 += sacc[nt][2];
            sacc[nt][3] = __expf(sacc[nt][3] - mn1); rs1 += sacc[nt][3];
        }
        rs0 += __shfl_xor_sync(0xffffffffu, rs0, 1);
        rs0 += __shfl_xor_sync(0xffffffffu, rs0, 2);
        rs1 += __shfl_xor_sync(0xffffffffu, rs1, 1);
        rs1 += __shfl_xor_sync(0xffffffffu, rs1, 2);
        l_[0] = l_[0]*cr0 + rs0; l_[1] = l_[1]*cr1 + rs1;
#pragma unroll
        for (int nt = 0; nt < 8; nt++) {
            oacc[nt][0] *= cr0; oacc[nt][1] *= cr0;
            oacc[nt][2] *= cr1; oacc[nt][3] *= cr1;
        }

        {
            int prow = wid*16 + r;
#pragma unroll
            for (int nt = 0; nt < 8; nt++) {
                float* dst = QP + (nt >> 2) * 4096;
                int kk = (nt & 3)*8 + 2*q;
                dst[swz(prow,   kk  )] = tf32r(sacc[nt][0]);
                dst[swz(prow,   kk+1)] = tf32r(sacc[nt][1]);
                dst[swz(prow+8, kk  )] = tf32r(sacc[nt][2]);
                dst[swz(prow+8, kk+1)] = tf32r(sacc[nt][3]);
            }
        }
        __syncwarp();

#pragma unroll
        for (int kc = 0; kc < 2; kc++)
#pragma unroll
            for (int h = 0; h < 2; h++) {
                const float* sP = QP + kc*4096;
                const float* sV = Vs + kc*2048;
                uint32_t ap[2][4];
#pragma unroll
                for (int rr = 0; rr < 2; rr++) {
                    int row = wid*16 + r + rr*8;
                    uint4 v4 = *reinterpret_cast<const uint4*>(
                        sP + row*32 + ((((q<<1)|h) ^ (row & 7)) << 2));
                    ap[rr][0]=v4.x; ap[rr][1]=v4.y; ap[rr][2]=v4.z; ap[rr][3]=v4.w;
                }
#pragma unroll
                for (int sh = 0; sh < 2; sh++) {
                    int e = sh*2;
                    uint32_t a[4] = { ap[0][e], ap[1][e], ap[0][e+1], ap[1][e+1] };
#pragma unroll
                    for (int nt = 0; nt < 8; nt++) {
                        int row = nt*8 + r;
                        uint2 bv = *reinterpret_cast<const uint2*>(
                            sV + row*32 + ((((q<<1)|h) ^ (row & 7)) << 2) + e);
                        uint32_t b[2] = { bv.x, bv.y };
                        mma_tf32(oacc[nt], a, b);
                    }
                }
            }
        __syncthreads();
    }

    int b = bh >> 3, hh = bh & 7;
#pragma unroll
    for (int i = 0; i < 2; i++) {
        float inv = 1.0f / l_[i];
        int t = qt*128 + wid*16 + r + i*8;
        size_t base = ((size_t)(b*NT + t))*ND + hh*NDK;
#pragma unroll
        for (int nt = 0; nt < 8; nt++) {
            float2 v2 = make_float2(tf32r(oacc[nt][2*i]*inv), tf32r(oacc[nt][2*i+1]*inv));
            *reinterpret_cast<float2*>(out + base + nt*8 + 2*q) = v2;
        }
    }
}

// ---------------- Group attention over B (rounded output -> GEMM A) -----------
__global__ void __launch_bounds__(64) group_attn_kernel(
    const float* __restrict__ Qg, const float* __restrict__ Kg,
    const float* __restrict__ Vg, float* __restrict__ out)
{
    int t = blockIdx.x, h = blockIdx.y;
    int d = threadIdx.x;
    __shared__ float qs[8][68], ks[8][68], vs[8][68], ps[8][8];
#pragma unroll
    for (int b = 0; b < 8; b++) {
        size_t idx = ((size_t)(b*NT + t))*ND + h*NDK + d;
        qs[b][d] = Qg[idx]; ks[b][d] = Kg[idx]; vs[b][d] = Vg[idx];
    }
    __syncthreads();
    int bq = d >> 3, bk = d & 7;
    float s = 0.f;
#pragma unroll 16
    for (int dd = 0; dd < 64; dd++) s = fmaf(qs[bq][dd], ks[bk][dd], s);
    s *= 0.125f;
    float mx = s;
#pragma unroll
    for (int off = 4; off; off >>= 1) mx = fmaxf(mx, __shfl_xor_sync(0xffffffffu, mx, off));
    float p = __expf(s - mx);
    float sum = p;
#pragma unroll
    for (int off = 4; off; off >>= 1) sum += __shfl_xor_sync(0xffffffffu, sum, off);
    ps[bq][bk] = p / sum;
    __syncthreads();
#pragma unroll
    for (int b = 0; b < 8; b++) {
        float a = 0.f;
#pragma unroll
        for (int b2 = 0; b2 < 8; b2++) a = fmaf(ps[b][b2], vs[b2][d], a);
        out[((size_t)(b*NT + t))*ND + h*NDK + d] = tf32r(a);
    }
}

// ---------------- launch ----------------
extern "C" void kernel_launch(void* const* d_in, const int* in_sizes, int n_in,
                              void* d_out, int out_size)
{
    (void)in_sizes; (void)n_in; (void)out_size;
    const float* h    = (const float*)d_in[0];
    const float* lnt  = (const float*)d_in[4];
    const float* lng  = (const float*)d_in[5];
    float* out = (float*)d_out;

    float *normed, *q, *k, *v, *attn, *h1, *wt, *ctab, *stab;
    cudaGetSymbolAddress((void**)&normed, g_normed);
    cudaGetSymbolAddress((void**)&q,      g_qb);
    cudaGetSymbolAddress((void**)&k,      g_kb);
    cudaGetSymbolAddress((void**)&v,      g_vb);
    cudaGetSymbolAddress((void**)&attn,   g_attnb);
    cudaGetSymbolAddress((void**)&h1,     g_h1);
    cudaGetSymbolAddress((void**)&wt,     g_wt);
    cudaGetSymbolAddress((void**)&ctab,   g_ctab);
    cudaGetSymbolAddress((void**)&stab,   g_stab);

    const int FL_SMEM_BYTES = FL_SMEM_FLOATS * 4;
    cudaFuncSetAttribute(gemm_f<0>, cudaFuncAttributeMaxDynamicSharedMemorySize, GSMEM_BYTES);
    cudaFuncSetAttribute(gemm_f<1>, cudaFuncAttributeMaxDynamicSharedMemorySize, GSMEM_BYTES);
    cudaFuncSetAttribute(gemm_f<2>, cudaFuncAttributeMaxDynamicSharedMemorySize, GSMEM_BYTES);
    cudaFuncSetAttribute(flash_mma, cudaFuncAttributeMaxDynamicSharedMemorySize, FL_SMEM_BYTES);

    WPtrs wp;
    for (int i = 0; i < 8; i++) wp.p[i] = (const float*)d_in[6 + i];
    transpose_w<<<dim3(16,16,8), dim3(32,8)>>>(wp, wt);
    rope_table_k<<<8, 128>>>(ctab, stab);

    const size_t WSZ = (size_t)ND*ND;
    dim3 gq(12, NTOK/128);   // fused QKV
    dim3 gr(4,  NTOK/128);   // single GEMM + residual

    // --- time attention ---
    rmsnorm_kernel<<<NTOK, 128>>>(h, lnt, normed);
    gemm_f<1><<<gq, 256, GSMEM_BYTES>>>(normed, wt, nullptr, q, k, v, ctab, stab);
    flash_mma<<<dim3(NT/128, NB*NH), 256, FL_SMEM_BYTES>>>(q, k, v, attn);
    gemm_f<0><<<gr, 256, GSMEM_BYTES>>>(attn, wt + 3*WSZ, h, h1, nullptr, nullptr, ctab, stab);

    // --- group attention ---
    rmsnorm_kernel<<<NTOK, 128>>>(h1, lng, normed);
    gemm_f<2><<<gq, 256, GSMEM_BYTES>>>(normed, wt + 4*WSZ, nullptr, q, k, v, ctab, stab);
    group_attn_kernel<<<dim3(NT, NH), 64>>>(q, k, v, attn);
    gemm_f<0><<<gr, 256, GSMEM_BYTES>>>(attn, wt + 7*WSZ, h1, out, nullptr, nullptr, ctab, stab);
}

// round 8
// speedup vs baseline: 1.7331x; 1.7331x over previous
#include <cuda_runtime.h>
#include <math.h>
#include <stdint.h>

#define NB 8
#define NT 1024
#define ND 512
#define NH 8
#define NDK 64
#define NTOK (NB*NT)

// ---------------- scratch (no allocation allowed) ----------------
static __device__ float g_normed[NTOK*ND];
static __device__ float g_qb[NTOK*ND];
static __device__ float g_kb[NTOK*ND];
static __device__ float g_vb[NTOK*ND];       // V stored [b,h,dk,t] for flash
static __device__ float g_attnb[NTOK*ND];
static __device__ float g_h1[NTOK*ND];
static __device__ float g_wt[8*ND*ND];       // transposed tf32-rounded weights [n][k]
static __device__ float g_ctab[32*NT];
static __device__ float g_stab[32*NT];

// ---------------- PTX helpers (plain sm_80 features, OK for .target sm_103) --
__device__ __forceinline__ float tf32r(float x) {
    uint32_t u = __float_as_uint(x), o;
    asm("cvt.rna.tf32.f32 %0, %1;" : "=r"(o) : "r"(u));
    return __uint_as_float(o);
}
__device__ __forceinline__ void mma_tf32(float* c, const uint32_t* a, const uint32_t* b) {
    asm volatile("mma.sync.aligned.m16n8k8.row.col.f32.tf32.tf32.f32 "
        "{%0,%1,%2,%3}, {%4,%5,%6,%7}, {%8,%9}, {%0,%1,%2,%3};"
        : "+f"(c[0]), "+f"(c[1]), "+f"(c[2]), "+f"(c[3])
        : "r"(a[0]), "r"(a[1]), "r"(a[2]), "r"(a[3]), "r"(b[0]), "r"(b[1]));
}
__device__ __forceinline__ uint32_t smem_u32(const void* p) {
    uint32_t a;
    asm("{ .reg .u64 t; cvta.to.shared.u64 t, %1; cvt.u32.u64 %0, t; }" : "=r"(a) : "l"(p));
    return a;
}
#define CP_ASYNC16(dst, src) \
    asm volatile("cp.async.cg.shared.global [%0], [%1], 16;" :: "r"(dst), "l"(src))
#define CP_COMMIT() asm volatile("cp.async.commit_group;")
#define CP_WAIT(n)  asm volatile("cp.async.wait_group %0;" :: "n"(n))
#define LDSM_X4(r, addr) \
    asm volatile("ldmatrix.sync.aligned.m8n8.x4.shared.b16 {%0,%1,%2,%3}, [%4];" \
        : "=r"((r)[0]), "=r"((r)[1]), "=r"((r)[2]), "=r"((r)[3]) : "r"(addr))

// ---------------- weight transpose + tf32 rounding ----------------
struct WPtrs { const float* p[8]; };
__global__ void __launch_bounds__(256) transpose_w(WPtrs ws, float* wt) {
    __shared__ float tile[32][33];
    const float* W = ws.p[blockIdx.z];
    float* O = wt + (size_t)blockIdx.z * (ND*ND);
    int n = blockIdx.x * 32 + threadIdx.x;
    int k0 = blockIdx.y * 32;
    for (int i = threadIdx.y; i < 32; i += 8)
        tile[i][threadIdx.x] = W[(size_t)(k0 + i) * ND + n];
    __syncthreads();
    int k = k0 + threadIdx.x;
    int nb = blockIdx.x * 32;
    for (int i = threadIdx.y; i < 32; i += 8)
        O[(size_t)(nb + i) * ND + k] = tf32r(tile[threadIdx.x][i]);
}

// ---------------- rope tables ----------------
__global__ void rope_table_k(float* ct, float* st) {
    int t = blockIdx.x * 128 + threadIdx.x;
#pragma unroll
    for (int j = 0; j < 32; j++) {
        float inv = exp2f(-((float)(2 * j) * (1.0f/NDK)) * 13.287712379549449f);
        float sn, cs;
        sincosf((float)t * inv, &sn, &cs);
        ct[j * NT + t] = cs;
        st[j * NT + t] = sn;
    }
}

// ---------------- RMSNorm (tf32-rounded output feeds GEMM A) ----------------
__global__ void __launch_bounds__(128) rmsnorm_kernel(
    const float* __restrict__ x, const float* __restrict__ w, float* __restrict__ out)
{
    int token = blockIdx.x;
    int tid = threadIdx.x;
    const float4 v = reinterpret_cast<const float4*>(x + (size_t)token*ND)[tid];
    float ss = v.x*v.x + v.y*v.y + v.z*v.z + v.w*v.w;
#pragma unroll
    for (int off = 16; off; off >>= 1) ss += __shfl_xor_sync(0xffffffffu, ss, off);
    __shared__ float red[4];
    if ((tid & 31) == 0) red[tid >> 5] = ss;
    __syncthreads();
    float tot = red[0] + red[1] + red[2] + red[3];
    float r = rsqrtf(tot * (1.0f/ND) + 1e-6f);
    const float4 wv = reinterpret_cast<const float4*>(w)[tid];
    float4 o;
    o.x = tf32r(v.x*r*wv.x); o.y = tf32r(v.y*r*wv.y);
    o.z = tf32r(v.z*r*wv.z); o.w = tf32r(v.w*r*wv.w);
    reinterpret_cast<float4*>(out + (size_t)token*ND)[tid] = o;
}

// ======================= cp.async + ldmatrix tf32 GEMM (as R7) =================
// MODE 0: C+R flat; MODE 1: fused QKV time (rope q*0.125 rounded, rope k rounded,
// v [b,h,dk,t] rounded); MODE 2: fused QKV group flat.
#define GSMEM_BYTES 98304

template<int MODE>
__global__ void __launch_bounds__(256, 2) gemm_f(
    const float* __restrict__ A, const float* __restrict__ Bt,
    const float* __restrict__ R,
    float* __restrict__ o0, float* __restrict__ o1, float* __restrict__ o2,
    const float* __restrict__ ctab, const float* __restrict__ stab)
{
    extern __shared__ float sm[];
    const int tid = threadIdx.x;
    const int wid = tid >> 5, lane = tid & 31;
    const int warp_m = wid >> 2, warp_n = wid & 3;
    const int r = lane >> 2, q = lane & 3;
    const int m0 = blockIdx.y * 128;
    const int n0 = blockIdx.x * 128;

    const float* Ap = A + (size_t)m0 * ND;
    const float* Bp = Bt + (size_t)n0 * ND;
    const uint32_t sbase = smem_u32(sm);
    const int crow = tid >> 3, cgb = tid & 7;

    float acc[4][4][4];
#pragma unroll
    for (int mt = 0; mt < 4; mt++)
#pragma unroll
        for (int nt = 0; nt < 4; nt++)
#pragma unroll
            for (int i = 0; i < 4; i++) acc[mt][nt][i] = 0.f;

#pragma unroll
    for (int s = 0; s < 3; s++) {
        uint32_t sa = sbase + s * 32768, sb = sa + 16384;
        int kc = s * 32;
#pragma unroll
        for (int u = 0; u < 4; u++) {
            int rr = crow + u*32;
            uint32_t off = (uint32_t)(rr*128 + ((cgb ^ (rr & 7)) << 4));
            CP_ASYNC16(sa + off, Ap + (size_t)rr*ND + kc + cgb*4);
            CP_ASYNC16(sb + off, Bp + (size_t)rr*ND + kc + cgb*4);
        }
        CP_COMMIT();
    }

    const int mi = lane >> 3, mrow = lane & 7;

    for (int kt = 0; kt < 16; kt++) {
        if (kt <= 13)      CP_WAIT(2);
        else if (kt == 14) CP_WAIT(1);
        else               CP_WAIT(0);
        __syncthreads();

        uint32_t stA = sbase + (kt % 3) * 32768;
        uint32_t stB = stA + 16384;

#pragma unroll
        for (int kb = 0; kb < 4; kb++) {
            uint32_t a[4][4], bq[2][4];
#pragma unroll
            for (int mt = 0; mt < 4; mt++) {
                int row = warp_m*64 + mt*16 + (mi & 1)*8 + mrow;
                int gb = 2*kb + (mi >> 1);
                LDSM_X4(a[mt], stA + row*128 + ((gb ^ (row & 7)) << 4));
            }
#pragma unroll
            for (int np = 0; np < 2; np++) {
                int row = warp_n*32 + (2*np + (mi >> 1))*8 + mrow;
                int gb = 2*kb + (mi & 1);
                LDSM_X4(bq[np], stB + row*128 + ((gb ^ (row & 7)) << 4));
            }
#pragma unroll
            for (int mt = 0; mt < 4; mt++)
#pragma unroll
                for (int nt = 0; nt < 4; nt++)
                    mma_tf32(acc[mt][nt], a[mt], &bq[nt >> 1][(nt & 1) * 2]);
        }
        __syncthreads();

        if (kt + 3 < 16) {
            int s = (kt + 3) % 3, kc = (kt + 3) * 32;
            uint32_t sa = sbase + s * 32768, sb = sa + 16384;
#pragma unroll
            for (int u = 0; u < 4; u++) {
                int rr = crow + u*32;
                uint32_t off = (uint32_t)(rr*128 + ((cgb ^ (rr & 7)) << 4));
                CP_ASYNC16(sa + off, Ap + (size_t)rr*ND + kc + cgb*4);
                CP_ASYNC16(sb + off, Bp + (size_t)rr*ND + kc + cgb*4);
            }
            CP_COMMIT();
        }
    }

    // ---- epilogue: stage C in SMEM ----
    float* Cs = sm;
#pragma unroll
    for (int mt = 0; mt < 4; mt++)
#pragma unroll
        for (int nt = 0; nt < 4; nt++) {
            int rb = warp_m*64 + mt*16 + r;
            int cb = warp_n*32 + nt*8 + 2*q;
            Cs[rb*132 + cb]         = acc[mt][nt][0];
            Cs[rb*132 + cb + 1]     = acc[mt][nt][1];
            Cs[(rb+8)*132 + cb]     = acc[mt][nt][2];
            Cs[(rb+8)*132 + cb + 1] = acc[mt][nt][3];
        }
    __syncthreads();

    const int row = tid & 127, hc = tid >> 7;
    const int grow = m0 + row;
    const int bb = grow >> 10, t = grow & (NT - 1);
    const float* cr = Cs + row*132 + hc*64;

    if (MODE == 0) {
        size_t base = (size_t)grow * ND + n0 + hc*64;
#pragma unroll
        for (int v = 0; v < 16; v++) {
            float4 x = *reinterpret_cast<const float4*>(cr + 4*v);
            float4 r4 = *reinterpret_cast<const float4*>(R + base + 4*v);
            x.x += r4.x; x.y += r4.y; x.z += r4.z; x.w += r4.w;
            *reinterpret_cast<float4*>(o0 + base + 4*v) = x;
        }
    } else if (MODE == 1) {
        int w = blockIdx.x >> 2;
        int head = (blockIdx.x & 3)*2 + hc;
        if (w < 2) {   // rope -> q (pre-scaled) or k, rounded, [b,h,t,dk]
            float* o = (w == 0) ? o0 : o1;
            float scale = (w == 0) ? 0.125f : 1.0f;
            size_t obase = ((size_t)(bb*NH + head)*NT + t)*NDK;
            float lo[32], hi[32];
#pragma unroll
            for (int j = 0; j < 32; j++) {
                float cs = ctab[j*NT + t], sn = stab[j*NT + t];
                float l0 = cr[j], h0 = cr[j + 32];
                lo[j] = tf32r((l0*cs - h0*sn) * scale);
                hi[j] = tf32r((h0*cs + l0*sn) * scale);
            }
#pragma unroll
            for (int v = 0; v < 8; v++) {
                *reinterpret_cast<float4*>(o + obase + 4*v)      = *reinterpret_cast<float4*>(lo + 4*v);
                *reinterpret_cast<float4*>(o + obase + 32 + 4*v) = *reinterpret_cast<float4*>(hi + 4*v);
            }
        } else {       // v -> [b,h,dk,t], rounded
            size_t obase = ((size_t)(bb*NH + head)*NDK)*NT + t;
#pragma unroll
            for (int j = 0; j < 64; j++)
                o2[obase + (size_t)j*NT] = tf32r(cr[j]);
        }
    } else {           // MODE 2: flat q/k/v for group attention
        int w = blockIdx.x >> 2;
        float* o = (w == 0) ? o0 : (w == 1) ? o1 : o2;
        size_t base = (size_t)grow * ND + (blockIdx.x & 3)*128 + hc*64;
#pragma unroll
        for (int v = 0; v < 16; v++)
            *reinterpret_cast<float4*>(o + base + 4*v) =
                *reinterpret_cast<const float4*>(cr + 4*v);
    }
}

// ======================= Flash attention: cp.async + ldmatrix ===================
// grid (NT/128, NB*NH), 256 threads / 8 warps; warp = 16 q-rows x 64 keys.
// Inputs pre-rounded tf32; Q pre-scaled by 0.125. V is [b,h,dk,t].
// SMEM (bytes): QP [128][64] @0 (Q then P); K stages @32K+st*16K; V @64K+st*16K.
#define FL_SMEM_BYTES 98304

__global__ void __launch_bounds__(256, 2) flash_mma(
    const float* __restrict__ Q, const float* __restrict__ K,
    const float* __restrict__ Vt, float* __restrict__ out)
{
    extern __shared__ float sm[];
    float* QP = sm;
    const uint32_t sb = smem_u32(sm);
    const int tid = threadIdx.x, wid = tid >> 5, lane = tid & 31;
    const int mi = lane >> 3, mrow = lane & 7;
    const int r = lane >> 2, q = lane & 3;
    const int qt = blockIdx.x, bh = blockIdx.y;
    const float* qp = Q  + ((size_t)bh*NT + qt*128)*NDK;
    const float* kp = K  + (size_t)bh*NT*NDK;
    const float* vp = Vt + (size_t)bh*NDK*NT;
    const int c16 = tid >> 4, cgb = tid & 15;

    // ---- Q: 128x64 via cp.async (group 0) ----
#pragma unroll
    for (int u = 0; u < 8; u++) {
        int row = c16 + u*16;
        uint32_t off = (uint32_t)(row*256 + ((cgb ^ (row & 7)) << 4));
        CP_ASYNC16(sb + off, qp + (size_t)row*NDK + cgb*4);
    }
    CP_COMMIT();

    // ---- K/V stage loader ----
    auto loadKV = [&](int st, int kt) {
#pragma unroll
        for (int u = 0; u < 4; u++) {
            int row = c16 + u*16;
            uint32_t off = (uint32_t)(row*256 + ((cgb ^ (row & 7)) << 4));
            CP_ASYNC16(sb + 32768 + st*16384 + off, kp + (size_t)(kt*64 + row)*NDK + cgb*4);
            CP_ASYNC16(sb + 65536 + st*16384 + off, vp + (size_t)row*NT + kt*64 + cgb*4);
        }
        CP_COMMIT();
    };
    loadKV(0, 0);
    loadKV(1, 1);

    CP_WAIT(2);          // Q ready
    __syncthreads();

    // ---- persistent Q A-fragments ----
    uint32_t aq[8][4];
#pragma unroll
    for (int kb = 0; kb < 8; kb++) {
        int row = wid*16 + (mi & 1)*8 + mrow;
        int gb = 2*kb + (mi >> 1);
        LDSM_X4(aq[kb], sb + row*256 + ((gb ^ (row & 7)) << 4));
    }
    __syncthreads();     // QP now reusable as P

    float m_[2] = {-1e30f, -1e30f}, l_[2] = {0.f, 0.f};
    float oacc[8][4];
#pragma unroll
    for (int nt = 0; nt < 8; nt++)
#pragma unroll
        for (int i = 0; i < 4; i++) oacc[nt][i] = 0.f;

    for (int kt = 0; kt < 16; kt++) {
        if (kt < 15) CP_WAIT(1); else CP_WAIT(0);
        __syncthreads();
        const uint32_t kbuf = sb + 32768 + (kt & 1)*16384;
        const uint32_t vbuf = sb + 65536 + (kt & 1)*16384;

        // ---- S = Q @ K^T ----
        float sacc[8][4];
#pragma unroll
        for (int nt = 0; nt < 8; nt++)
#pragma unroll
            for (int i = 0; i < 4; i++) sacc[nt][i] = 0.f;
#pragma unroll
        for (int kb = 0; kb < 8; kb++) {
#pragma unroll
            for (int nph = 0; nph < 2; nph++) {
                uint32_t bq[2][4];
#pragma unroll
                for (int np = 0; np < 2; np++) {
                    int row = (2*(nph*2 + np) + (mi >> 1))*8 + mrow;
                    int gb = 2*kb + (mi & 1);
                    LDSM_X4(bq[np], kbuf + row*256 + ((gb ^ (row & 7)) << 4));
                }
#pragma unroll
                for (int nt = 0; nt < 4; nt++)
                    mma_tf32(sacc[nph*4 + nt], aq[kb], &bq[nt >> 1][(nt & 1) * 2]);
            }
        }

        // ---- online softmax ----
        float tmax0 = -1e30f, tmax1 = -1e30f;
#pragma unroll
        for (int nt = 0; nt < 8; nt++) {
            tmax0 = fmaxf(tmax0, fmaxf(sacc[nt][0], sacc[nt][1]));
            tmax1 = fmaxf(tmax1, fmaxf(sacc[nt][2], sacc[nt][3]));
        }
        tmax0 = fmaxf(tmax0, __shfl_xor_sync(0xffffffffu, tmax0, 1));
        tmax0 = fmaxf(tmax0, __shfl_xor_sync(0xffffffffu, tmax0, 2));
        tmax1 = fmaxf(tmax1, __shfl_xor_sync(0xffffffffu, tmax1, 1));
        tmax1 = fmaxf(tmax1, __shfl_xor_sync(0xffffffffu, tmax1, 2));
        float mn0 = fmaxf(m_[0], tmax0), mn1 = fmaxf(m_[1], tmax1);
        float cr0 = __expf(m_[0] - mn0), cr1 = __expf(m_[1] - mn1);
        m_[0] = mn0; m_[1] = mn1;
        float rs0 = 0.f, rs1 = 0.f;
#pragma unroll
        for (int nt = 0; nt < 8; nt++) {
            sacc[nt][0] = __expf(sacc[nt][0] - mn0); rs0 += sacc[nt][0];
            sacc[nt][1] = __expf(sacc[nt][1] - mn0); rs0 += sacc[nt][1];
            sacc[nt][2] = __expf(sacc[nt][2] - mn1); rs1 += sacc[nt][2];
            sacc[nt][3] = __expf(sacc[nt][3] - mn1); rs1 += sacc[nt][3];
        }
        rs0 += __shfl_xor_sync(0xffffffffu, rs0, 1);
        rs0 += __shfl_xor_sync(0xffffffffu, rs0, 2);
        rs1 += __shfl_xor_sync(0xffffffffu, rs1, 1);
        rs1 += __shfl_xor_sync(0xffffffffu, rs1, 2);
        l_[0] = l_[0]*cr0 + rs0; l_[1] = l_[1]*cr1 + rs1;
#pragma unroll
        for (int nt = 0; nt < 8; nt++) {
            oacc[nt][0] *= cr0; oacc[nt][1] *= cr0;
            oacc[nt][2] *= cr1; oacc[nt][3] *= cr1;
        }

        // ---- P store (A-layout, warp-local rows, tf32-rounded) ----
        {
            int prow = wid*16 + r;
#pragma unroll
            for (int nt = 0; nt < 8; nt++) {
                int col = nt*8 + 2*q;
                int gb = col >> 2, e = col & 3;
                int w0 = ((gb ^ r) << 2) + e;
                *reinterpret_cast<float2*>(QP + prow*64 + w0) =
                    make_float2(tf32r(sacc[nt][0]), tf32r(sacc[nt][1]));
                *reinterpret_cast<float2*>(QP + (prow+8)*64 + w0) =
                    make_float2(tf32r(sacc[nt][2]), tf32r(sacc[nt][3]));
            }
        }
        __syncwarp();

        // ---- O += P @ V ----
#pragma unroll
        for (int kb = 0; kb < 8; kb++) {
            uint32_t ap[4];
            {
                int row = wid*16 + (mi & 1)*8 + mrow;
                int gb = 2*kb + (mi >> 1);
                LDSM_X4(ap, sb + row*256 + ((gb ^ (row & 7)) << 4));
            }
#pragma unroll
            for (int nph = 0; nph < 2; nph++) {
                uint32_t bv[2][4];
#pragma unroll
                for (int np = 0; np < 2; np++) {
                    int row = (2*(nph*2 + np) + (mi >> 1))*8 + mrow;
                    int gb = 2*kb + (mi & 1);
                    LDSM_X4(bv[np], vbuf + row*256 + ((gb ^ (row & 7)) << 4));
                }
#pragma unroll
                for (int nt = 0; nt < 4; nt++)
                    mma_tf32(oacc[nph*4 + nt], ap, &bv[nt >> 1][(nt & 1) * 2]);
            }
        }
        __syncthreads();            // all reads of stage kt done
        if (kt + 2 < 16) loadKV(kt & 1, kt + 2);
    }

    // ---- write O: [token][512], rounded (feeds Wo GEMM) ----
    int b = bh >> 3, hh = bh & 7;
#pragma unroll
    for (int i = 0; i < 2; i++) {
        float inv = 1.0f / l_[i];
        int t = qt*128 + wid*16 + r + i*8;
        size_t base = ((size_t)(b*NT + t))*ND + hh*NDK;
#pragma unroll
        for (int nt = 0; nt < 8; nt++) {
            float2 v2 = make_float2(tf32r(oacc[nt][2*i]*inv), tf32r(oacc[nt][2*i+1]*inv));
            *reinterpret_cast<float2*>(out + base + nt*8 + 2*q) = v2;
        }
    }
}

// ---------------- Group attention over B (rounded output -> GEMM A) -----------
__global__ void __launch_bounds__(64) group_attn_kernel(
    const float* __restrict__ Qg, const float* __restrict__ Kg,
    const float* __restrict__ Vg, float* __restrict__ out)
{
    int t = blockIdx.x, h = blockIdx.y;
    int d = threadIdx.x;
    __shared__ float qs[8][68], ks[8][68], vs[8][68], ps[8][8];
#pragma unroll
    for (int b = 0; b < 8; b++) {
        size_t idx = ((size_t)(b*NT + t))*ND + h*NDK + d;
        qs[b][d] = Qg[idx]; ks[b][d] = Kg[idx]; vs[b][d] = Vg[idx];
    }
    __syncthreads();
    int bq = d >> 3, bk = d & 7;
    float s = 0.f;
#pragma unroll 16
    for (int dd = 0; dd < 64; dd++) s = fmaf(qs[bq][dd], ks[bk][dd], s);
    s *= 0.125f;
    float mx = s;
#pragma unroll
    for (int off = 4; off; off >>= 1) mx = fmaxf(mx, __shfl_xor_sync(0xffffffffu, mx, off));
    float p = __expf(s - mx);
    float sum = p;
#pragma unroll
    for (int off = 4; off; off >>= 1) sum += __shfl_xor_sync(0xffffffffu, sum, off);
    ps[bq][bk] = p / sum;
    __syncthreads();
#pragma unroll
    for (int b = 0; b < 8; b++) {
        float a = 0.f;
#pragma unroll
        for (int b2 = 0; b2 < 8; b2++) a = fmaf(ps[b][b2], vs[b2][d], a);
        out[((size_t)(b*NT + t))*ND + h*NDK + d] = tf32r(a);
    }
}

// ---------------- launch ----------------
extern "C" void kernel_launch(void* const* d_in, const int* in_sizes, int n_in,
                              void* d_out, int out_size)
{
    (void)in_sizes; (void)n_in; (void)out_size;
    const float* h    = (const float*)d_in[0];
    const float* lnt  = (const float*)d_in[4];
    const float* lng  = (const float*)d_in[5];
    float* out = (float*)d_out;

    float *normed, *q, *k, *v, *attn, *h1, *wt, *ctab, *stab;
    cudaGetSymbolAddress((void**)&normed, g_normed);
    cudaGetSymbolAddress((void**)&q,      g_qb);
    cudaGetSymbolAddress((void**)&k,      g_kb);
    cudaGetSymbolAddress((void**)&v,      g_vb);
    cudaGetSymbolAddress((void**)&attn,   g_attnb);
    cudaGetSymbolAddress((void**)&h1,     g_h1);
    cudaGetSymbolAddress((void**)&wt,     g_wt);
    cudaGetSymbolAddress((void**)&ctab,   g_ctab);
    cudaGetSymbolAddress((void**)&stab,   g_stab);

    cudaFuncSetAttribute(gemm_f<0>, cudaFuncAttributeMaxDynamicSharedMemorySize, GSMEM_BYTES);
    cudaFuncSetAttribute(gemm_f<1>, cudaFuncAttributeMaxDynamicSharedMemorySize, GSMEM_BYTES);
    cudaFuncSetAttribute(gemm_f<2>, cudaFuncAttributeMaxDynamicSharedMemorySize, GSMEM_BYTES);
    cudaFuncSetAttribute(flash_mma, cudaFuncAttributeMaxDynamicSharedMemorySize, FL_SMEM_BYTES);

    WPtrs wp;
    for (int i = 0; i < 8; i++) wp.p[i] = (const float*)d_in[6 + i];
    transpose_w<<<dim3(16,16,8), dim3(32,8)>>>(wp, wt);
    rope_table_k<<<8, 128>>>(ctab, stab);

    const size_t WSZ = (size_t)ND*ND;
    dim3 gq(12, NTOK/128);   // fused QKV
    dim3 gr(4,  NTOK/128);   // single GEMM + residual

    // --- time attention ---
    rmsnorm_kernel<<<NTOK, 128>>>(h, lnt, normed);
    gemm_f<1><<<gq, 256, GSMEM_BYTES>>>(normed, wt, nullptr, q, k, v, ctab, stab);
    flash_mma<<<dim3(NT/128, NB*NH), 256, FL_SMEM_BYTES>>>(q, k, v, attn);
    gemm_f<0><<<gr, 256, GSMEM_BYTES>>>(attn, wt + 3*WSZ, h, h1, nullptr, nullptr, ctab, stab);

    // --- group attention ---
    rmsnorm_kernel<<<NTOK, 128>>>(h1, lng, normed);
    gemm_f<2><<<gq, 256, GSMEM_BYTES>>>(normed, wt + 4*WSZ, nullptr, q, k, v, ctab, stab);
    group_attn_kernel<<<dim3(NT, NH), 64>>>(q, k, v, attn);
    gemm_f<0><<<gr, 256, GSMEM_BYTES>>>(attn, wt + 7*WSZ, h1, out, nullptr, nullptr, ctab, stab);
}

// round 9
// speedup vs baseline: 2.5347x; 1.4625x over previous
#include <cuda_runtime.h>
#include <cuda_fp16.h>
#include <math.h>
#include <stdint.h>

#define NB 8
#define NT 1024
#define ND 512
#define NH 8
#define NDK 64
#define NTOK (NB*NT)

// ---------------- scratch (no allocation allowed) ----------------
static __device__ float g_normed[NTOK*ND];   // used as __half
static __device__ float g_qb[NTOK*ND];       // __half [b,h,t,dk] (time) / flat (group)
static __device__ float g_kb[NTOK*ND];       // __half
static __device__ float g_vb[NTOK*ND];       // __half [b,h,dk,t] (time) / flat (group)
static __device__ float g_attnb[NTOK*ND];    // __half [token][512]
static __device__ float g_h1[NTOK*ND];       // fp32 residual stream
static __device__ float g_wt[8*ND*ND];       // __half transposed weights [w][n][k]
static __device__ float g_ctab[32*NT];
static __device__ float g_stab[32*NT];

// ---------------- PTX helpers (plain sm_80 features, OK for .target sm_103) --
__device__ __forceinline__ void mma_f16(float* c, const uint32_t* a, const uint32_t* b) {
    asm volatile("mma.sync.aligned.m16n8k16.row.col.f32.f16.f16.f32 "
        "{%0,%1,%2,%3}, {%4,%5,%6,%7}, {%8,%9}, {%0,%1,%2,%3};"
        : "+f"(c[0]), "+f"(c[1]), "+f"(c[2]), "+f"(c[3])
        : "r"(a[0]), "r"(a[1]), "r"(a[2]), "r"(a[3]), "r"(b[0]), "r"(b[1]));
}
__device__ __forceinline__ uint32_t smem_u32(const void* p) {
    uint32_t a;
    asm("{ .reg .u64 t; cvta.to.shared.u64 t, %1; cvt.u32.u64 %0, t; }" : "=r"(a) : "l"(p));
    return a;
}
#define CP_ASYNC16(dst, src) \
    asm volatile("cp.async.cg.shared.global [%0], [%1], 16;" :: "r"(dst), "l"(src))
#define CP_COMMIT() asm volatile("cp.async.commit_group;")
#define CP_WAIT(n)  asm volatile("cp.async.wait_group %0;" :: "n"(n))
#define LDSM_X4(r, addr) \
    asm volatile("ldmatrix.sync.aligned.m8n8.x4.shared.b16 {%0,%1,%2,%3}, [%4];" \
        : "=r"((r)[0]), "=r"((r)[1]), "=r"((r)[2]), "=r"((r)[3]) : "r"(addr))

// ---------------- weight transpose + fp16 ----------------
struct WPtrs { const float* p[8]; };
__global__ void __launch_bounds__(256) transpose_w(WPtrs ws, __half* wt) {
    __shared__ float tile[32][33];
    const float* W = ws.p[blockIdx.z];
    __half* O = wt + (size_t)blockIdx.z * (ND*ND);
    int n = blockIdx.x * 32 + threadIdx.x;
    int k0 = blockIdx.y * 32;
    for (int i = threadIdx.y; i < 32; i += 8)
        tile[i][threadIdx.x] = W[(size_t)(k0 + i) * ND + n];
    __syncthreads();
    int k = k0 + threadIdx.x;
    int nb = blockIdx.x * 32;
    for (int i = threadIdx.y; i < 32; i += 8)
        O[(size_t)(nb + i) * ND + k] = __float2half_rn(tile[threadIdx.x][i]);
}

// ---------------- rope tables ----------------
__global__ void rope_table_k(float* ct, float* st) {
    int t = blockIdx.x * 128 + threadIdx.x;
#pragma unroll
    for (int j = 0; j < 32; j++) {
        float inv = exp2f(-((float)(2 * j) * (1.0f/NDK)) * 13.287712379549449f);
        float sn, cs;
        sincosf((float)t * inv, &sn, &cs);
        ct[j * NT + t] = cs;
        st[j * NT + t] = sn;
    }
}

// ---------------- RMSNorm (fp32 in, fp16 out) ----------------
__global__ void __launch_bounds__(128) rmsnorm_kernel(
    const float* __restrict__ x, const float* __restrict__ w, __half* __restrict__ out)
{
    int token = blockIdx.x;
    int tid = threadIdx.x;
    const float4 v = reinterpret_cast<const float4*>(x + (size_t)token*ND)[tid];
    float ss = v.x*v.x + v.y*v.y + v.z*v.z + v.w*v.w;
#pragma unroll
    for (int off = 16; off; off >>= 1) ss += __shfl_xor_sync(0xffffffffu, ss, off);
    __shared__ float red[4];
    if ((tid & 31) == 0) red[tid >> 5] = ss;
    __syncthreads();
    float tot = red[0] + red[1] + red[2] + red[3];
    float r = rsqrtf(tot * (1.0f/ND) + 1e-6f);
    const float4 wv = reinterpret_cast<const float4*>(w)[tid];
    __half2 h01 = __floats2half2_rn(v.x*r*wv.x, v.y*r*wv.y);
    __half2 h23 = __floats2half2_rn(v.z*r*wv.z, v.w*r*wv.w);
    uint2 st;
    st.x = *reinterpret_cast<uint32_t*>(&h01);
    st.y = *reinterpret_cast<uint32_t*>(&h23);
    reinterpret_cast<uint2*>(out + (size_t)token*ND)[tid] = st;
}

// ======================= fp16 GEMM: cp.async + ldmatrix + m16n8k16 =============
// CTA 128x128, BK=64 halves (128B rows), 3-stage pipeline, 8 warps (2x4), warp 64x32.
// SMEM stage: A 16KB + B 16KB; row = 128B = 8 x 16B groups, group gb ^ (row&7).
// MODE 0: fp32 C + R -> o0 fp32 flat              (grid 4 x 64)
// MODE 1: fused QKV time -> half q(rope*0.125), half k(rope), half v [b,h,dk,t] (grid 12 x 64)
// MODE 2: fused QKV group -> half flat o0/o1/o2   (grid 12 x 64)
#define GSMEM_BYTES 98304

template<int MODE>
__global__ void __launch_bounds__(256, 2) gemm_h(
    const __half* __restrict__ A, const __half* __restrict__ Bt,
    const float* __restrict__ R,
    void* o0_, void* o1_, void* o2_,
    const float* __restrict__ ctab, const float* __restrict__ stab)
{
    extern __shared__ float sm[];
    const int tid = threadIdx.x;
    const int wid = tid >> 5, lane = tid & 31;
    const int warp_m = wid >> 2, warp_n = wid & 3;
    const int r = lane >> 2, q = lane & 3;
    const int mi = lane >> 3, mrow = lane & 7;
    const int m0 = blockIdx.y * 128;
    const int n0 = blockIdx.x * 128;

    const __half* Ap = A + (size_t)m0 * ND;
    const __half* Bp = Bt + (size_t)n0 * ND;
    const uint32_t sbase = smem_u32(sm);
    const int crow = tid >> 3, cgb = tid & 7;

    float acc[4][4][4];
#pragma unroll
    for (int mt = 0; mt < 4; mt++)
#pragma unroll
        for (int nt = 0; nt < 4; nt++)
#pragma unroll
            for (int i = 0; i < 4; i++) acc[mt][nt][i] = 0.f;

#pragma unroll
    for (int s = 0; s < 3; s++) {
        uint32_t sa = sbase + s * 32768, sb = sa + 16384;
        int kc = s * 64;
#pragma unroll
        for (int u = 0; u < 4; u++) {
            int rr = crow + u*32;
            uint32_t off = (uint32_t)(rr*128 + ((cgb ^ (rr & 7)) << 4));
            CP_ASYNC16(sa + off, Ap + (size_t)rr*ND + kc + cgb*8);
            CP_ASYNC16(sb + off, Bp + (size_t)rr*ND + kc + cgb*8);
        }
        CP_COMMIT();
    }

    for (int kt = 0; kt < 8; kt++) {
        if (kt <= 5)       CP_WAIT(2);
        else if (kt == 6)  CP_WAIT(1);
        else               CP_WAIT(0);
        __syncthreads();

        uint32_t stA = sbase + (kt % 3) * 32768;
        uint32_t stB = stA + 16384;

#pragma unroll
        for (int kb = 0; kb < 4; kb++) {
            uint32_t a[4][4], bq[2][4];
#pragma unroll
            for (int mt = 0; mt < 4; mt++) {
                int row = warp_m*64 + mt*16 + (mi & 1)*8 + mrow;
                int gb = 2*kb + (mi >> 1);
                LDSM_X4(a[mt], stA + row*128 + ((gb ^ (row & 7)) << 4));
            }
#pragma unroll
            for (int np = 0; np < 2; np++) {
                int row = warp_n*32 + np*16 + (mi >> 1)*8 + mrow;
                int gb = 2*kb + (mi & 1);
                LDSM_X4(bq[np], stB + row*128 + ((gb ^ (row & 7)) << 4));
            }
#pragma unroll
            for (int mt = 0; mt < 4; mt++)
#pragma unroll
                for (int nt = 0; nt < 4; nt++)
                    mma_f16(acc[mt][nt], a[mt], &bq[nt >> 1][(nt & 1) * 2]);
        }
        __syncthreads();

        if (kt + 3 < 8) {
            int s = (kt + 3) % 3, kc = (kt + 3) * 64;
            uint32_t sa = sbase + s * 32768, sb = sa + 16384;
#pragma unroll
            for (int u = 0; u < 4; u++) {
                int rr = crow + u*32;
                uint32_t off = (uint32_t)(rr*128 + ((cgb ^ (rr & 7)) << 4));
                CP_ASYNC16(sa + off, Ap + (size_t)rr*ND + kc + cgb*8);
                CP_ASYNC16(sb + off, Bp + (size_t)rr*ND + kc + cgb*8);
            }
            CP_COMMIT();
        }
    }

    // ---- epilogue: stage fp32 C in SMEM ----
    float* Cs = sm;
#pragma unroll
    for (int mt = 0; mt < 4; mt++)
#pragma unroll
        for (int nt = 0; nt < 4; nt++) {
            int rb = warp_m*64 + mt*16 + r;
            int cb = warp_n*32 + nt*8 + 2*q;
            Cs[rb*132 + cb]         = acc[mt][nt][0];
            Cs[rb*132 + cb + 1]     = acc[mt][nt][1];
            Cs[(rb+8)*132 + cb]     = acc[mt][nt][2];
            Cs[(rb+8)*132 + cb + 1] = acc[mt][nt][3];
        }
    __syncthreads();

    const int row = tid & 127, hc = tid >> 7;
    const int grow = m0 + row;
    const int bb = grow >> 10, t = grow & (NT - 1);
    const float* cr = Cs + row*132 + hc*64;

    if (MODE == 0) {
        float* o0 = (float*)o0_;
        size_t base = (size_t)grow * ND + n0 + hc*64;
#pragma unroll
        for (int v = 0; v < 16; v++) {
            float4 x = *reinterpret_cast<const float4*>(cr + 4*v);
            float4 r4 = *reinterpret_cast<const float4*>(R + base + 4*v);
            x.x += r4.x; x.y += r4.y; x.z += r4.z; x.w += r4.w;
            *reinterpret_cast<float4*>(o0 + base + 4*v) = x;
        }
    } else if (MODE == 1) {
        int w = blockIdx.x >> 2;
        int head = (blockIdx.x & 3)*2 + hc;
        if (w < 2) {   // rope -> half q (pre-scaled) or half k, [b,h,t,dk]
            __half* o = (w == 0) ? (__half*)o0_ : (__half*)o1_;
            float scale = (w == 0) ? 0.125f : 1.0f;
            size_t obase = ((size_t)(bb*NH + head)*NT + t)*NDK;
            float lo[32], hi[32];
#pragma unroll
            for (int j = 0; j < 32; j++) {
                float cs = ctab[j*NT + t], sn = stab[j*NT + t];
                float l0 = cr[j], h0 = cr[j + 32];
                lo[j] = (l0*cs - h0*sn) * scale;
                hi[j] = (h0*cs + l0*sn) * scale;
            }
            __half2* ol = reinterpret_cast<__half2*>(o + obase);
            __half2* oh = reinterpret_cast<__half2*>(o + obase + 32);
#pragma unroll
            for (int v = 0; v < 16; v++) {
                ol[v] = __floats2half2_rn(lo[2*v], lo[2*v+1]);
                oh[v] = __floats2half2_rn(hi[2*v], hi[2*v+1]);
            }
        } else {       // half v -> [b,h,dk,t]
            __half* o2 = (__half*)o2_;
            size_t obase = ((size_t)(bb*NH + head)*NDK)*NT + t;
#pragma unroll
            for (int j = 0; j < 64; j++)
                o2[obase + (size_t)j*NT] = __float2half_rn(cr[j]);
        }
    } else {           // MODE 2: half flat q/k/v
        int w = blockIdx.x >> 2;
        __half* o = (w == 0) ? (__half*)o0_ : (w == 1) ? (__half*)o1_ : (__half*)o2_;
        size_t base = (size_t)grow * ND + (blockIdx.x & 3)*128 + hc*64;
        __half2* op = reinterpret_cast<__half2*>(o + base);
#pragma unroll
        for (int v = 0; v < 32; v++)
            op[v] = __floats2half2_rn(cr[2*v], cr[2*v+1]);
    }
}

// ======================= Flash attention: fp16 cp.async + ldmatrix ==============
// grid (NT/128, NB*NH), 256 threads / 8 warps; warp = 16 q-rows x 64 keys.
// Q half [b,h,t,dk] pre-scaled 0.125; K half [b,h,t,dk]; V half [b,h,dk,t].
// SMEM bytes: QP [128][128B] @0 (Q then P); K @16K+st*8K; V @32K+st*8K.
#define FL_SMEM_BYTES 49152

__global__ void __launch_bounds__(256, 2) flash_h(
    const __half* __restrict__ Q, const __half* __restrict__ K,
    const __half* __restrict__ Vt, __half* __restrict__ out)
{
    extern __shared__ float sm[];
    const uint32_t sb = smem_u32(sm);
    char* smb = reinterpret_cast<char*>(sm);
    const int tid = threadIdx.x, wid = tid >> 5, lane = tid & 31;
    const int mi = lane >> 3, mrow = lane & 7;
    const int r = lane >> 2, q = lane & 3;
    const int qt = blockIdx.x, bh = blockIdx.y;
    const __half* qp = Q  + ((size_t)bh*NT + qt*128)*NDK;
    const __half* kp = K  + (size_t)bh*NT*NDK;
    const __half* vp = Vt + (size_t)bh*NDK*NT;
    const int crow = tid >> 3, cgb = tid & 7;

    // ---- Q: 128 rows x 128B via cp.async (group 0) ----
#pragma unroll
    for (int u = 0; u < 4; u++) {
        int row = crow + u*32;
        uint32_t off = (uint32_t)(row*128 + ((cgb ^ (row & 7)) << 4));
        CP_ASYNC16(sb + off, qp + (size_t)row*NDK + cgb*8);
    }
    CP_COMMIT();

    auto loadKV = [&](int st, int kt) {
#pragma unroll
        for (int u = 0; u < 2; u++) {
            int row = crow + u*32;
            uint32_t off = (uint32_t)(row*128 + ((cgb ^ (row & 7)) << 4));
            CP_ASYNC16(sb + 16384 + st*8192 + off, kp + (size_t)(kt*64 + row)*NDK + cgb*8);
            CP_ASYNC16(sb + 32768 + st*8192 + off, vp + (size_t)row*NT + kt*64 + cgb*8);
        }
        CP_COMMIT();
    };
    loadKV(0, 0);
    loadKV(1, 1);

    CP_WAIT(2);          // Q ready
    __syncthreads();

    // ---- persistent Q A-fragments (dk=64 -> 4 k16 blocks) ----
    uint32_t aq[4][4];
#pragma unroll
    for (int kb = 0; kb < 4; kb++) {
        int row = wid*16 + (mi & 1)*8 + mrow;
        int gb = 2*kb + (mi >> 1);
        LDSM_X4(aq[kb], sb + row*128 + ((gb ^ (row & 7)) << 4));
    }
    __syncthreads();     // QP now reusable as P

    float m_[2] = {-1e30f, -1e30f}, l_[2] = {0.f, 0.f};
    float oacc[8][4];
#pragma unroll
    for (int nt = 0; nt < 8; nt++)
#pragma unroll
        for (int i = 0; i < 4; i++) oacc[nt][i] = 0.f;

    for (int kt = 0; kt < 16; kt++) {
        if (kt < 15) CP_WAIT(1); else CP_WAIT(0);
        __syncthreads();
        const uint32_t kbuf = sb + 16384 + (kt & 1)*8192;
        const uint32_t vbuf = sb + 32768 + (kt & 1)*8192;

        // ---- S = Q @ K^T ----
        float sacc[8][4];
#pragma unroll
        for (int nt = 0; nt < 8; nt++)
#pragma unroll
            for (int i = 0; i < 4; i++) sacc[nt][i] = 0.f;
#pragma unroll
        for (int kb = 0; kb < 4; kb++) {
            uint32_t bq[4][4];
#pragma unroll
            for (int np = 0; np < 4; np++) {
                int row = np*16 + (mi >> 1)*8 + mrow;
                int gb = 2*kb + (mi & 1);
                LDSM_X4(bq[np], kbuf + row*128 + ((gb ^ (row & 7)) << 4));
            }
#pragma unroll
            for (int nt = 0; nt < 8; nt++)
                mma_f16(sacc[nt], aq[kb], &bq[nt >> 1][(nt & 1) * 2]);
        }

        // ---- online softmax (rows r -> 0/1, r+8 -> 2/3) ----
        float tmax0 = -1e30f, tmax1 = -1e30f;
#pragma unroll
        for (int nt = 0; nt < 8; nt++) {
            tmax0 = fmaxf(tmax0, fmaxf(sacc[nt][0], sacc[nt][1]));
            tmax1 = fmaxf(tmax1, fmaxf(sacc[nt][2], sacc[nt][3]));
        }
        tmax0 = fmaxf(tmax0, __shfl_xor_sync(0xffffffffu, tmax0, 1));
        tmax0 = fmaxf(tmax0, __shfl_xor_sync(0xffffffffu, tmax0, 2));
        tmax1 = fmaxf(tmax1, __shfl_xor_sync(0xffffffffu, tmax1, 1));
        tmax1 = fmaxf(tmax1, __shfl_xor_sync(0xffffffffu, tmax1, 2));
        float mn0 = fmaxf(m_[0], tmax0), mn1 = fmaxf(m_[1], tmax1);
        float cr0 = __expf(m_[0] - mn0), cr1 = __expf(m_[1] - mn1);
        m_[0] = mn0; m_[1] = mn1;
        float rs0 = 0.f, rs1 = 0.f;
#pragma unroll
        for (int nt = 0; nt < 8; nt++) {
            sacc[nt][0] = __expf(sacc[nt][0] - mn0); rs0 += sacc[nt][0];
            sacc[nt][1] = __expf(sacc[nt][1] - mn0); rs0 += sacc[nt][1];
            sacc[nt][2] = __expf(sacc[nt][2] - mn1); rs1 += sacc[nt][2];
            sacc[nt][3] = __expf(sacc[nt][3] - mn1); rs1 += sacc[nt][3];
        }
        rs0 += __shfl_xor_sync(0xffffffffu, rs0, 1);
        rs0 += __shfl_xor_sync(0xffffffffu, rs0, 2);
        rs1 += __shfl_xor_sync(0xffffffffu, rs1, 1);
        rs1 += __shfl_xor_sync(0xffffffffu, rs1, 2);
        l_[0] = l_[0]*cr0 + rs0; l_[1] = l_[1]*cr1 + rs1;
#pragma unroll
        for (int nt = 0; nt < 8; nt++) {
            oacc[nt][0] *= cr0; oacc[nt][1] *= cr0;
            oacc[nt][2] *= cr1; oacc[nt][3] *= cr1;
        }

        // ---- P store (half, A-layout, warp-local rows) ----
        {
            int prow = wid*16 + r;
            int grp = prow & 7;
#pragma unroll
            for (int nt = 0; nt < 8; nt++) {
                uint32_t b0 = (uint32_t)(prow*128 + (((nt ^ grp) << 4) + 4*q));
                uint32_t b1 = (uint32_t)((prow+8)*128 + (((nt ^ grp) << 4) + 4*q));
                *reinterpret_cast<__half2*>(smb + b0) = __floats2half2_rn(sacc[nt][0], sacc[nt][1]);
                *reinterpret_cast<__half2*>(smb + b1) = __floats2half2_rn(sacc[nt][2], sacc[nt][3]);
            }
        }
        __syncwarp();

        // ---- O += P @ V ----
#pragma unroll
        for (int kb = 0; kb < 4; kb++) {
            uint32_t ap[4];
            {
                int row = wid*16 + (mi & 1)*8 + mrow;
                int gb = 2*kb + (mi >> 1);
                LDSM_X4(ap, sb + row*128 + ((gb ^ (row & 7)) << 4));
            }
            uint32_t bv[4][4];
#pragma unroll
            for (int np = 0; np < 4; np++) {
                int row = np*16 + (mi >> 1)*8 + mrow;
                int gb = 2*kb + (mi & 1);
                LDSM_X4(bv[np], vbuf + row*128 + ((gb ^ (row & 7)) << 4));
            }
#pragma unroll
            for (int nt = 0; nt < 8; nt++)
                mma_f16(oacc[nt], ap, &bv[nt >> 1][(nt & 1) * 2]);
        }
        __syncthreads();
        if (kt + 2 < 16) loadKV(kt & 1, kt + 2);
    }

    // ---- write O: half [token][512] (feeds Wo GEMM) ----
    int b = bh >> 3, hh = bh & 7;
#pragma unroll
    for (int i = 0; i < 2; i++) {
        float inv = 1.0f / l_[i];
        int t = qt*128 + wid*16 + r + i*8;
        size_t base = ((size_t)(b*NT + t))*ND + hh*NDK;
#pragma unroll
        for (int nt = 0; nt < 8; nt++) {
            *reinterpret_cast<__half2*>(out + base + nt*8 + 2*q) =
                __floats2half2_rn(oacc[nt][2*i]*inv, oacc[nt][2*i+1]*inv);
        }
    }
}

// ---------------- Group attention over B (half in/out, fp32 math) -------------
__global__ void __launch_bounds__(64) group_attn_kernel(
    const __half* __restrict__ Qg, const __half* __restrict__ Kg,
    const __half* __restrict__ Vg, __half* __restrict__ out)
{
    int t = blockIdx.x, h = blockIdx.y;
    int d = threadIdx.x;
    __shared__ float qs[8][68], ks[8][68], vs[8][68], ps[8][8];
#pragma unroll
    for (int b = 0; b < 8; b++) {
        size_t idx = ((size_t)(b*NT + t))*ND + h*NDK + d;
        qs[b][d] = __half2float(Qg[idx]);
        ks[b][d] = __half2float(Kg[idx]);
        vs[b][d] = __half2float(Vg[idx]);
    }
    __syncthreads();
    int bq = d >> 3, bk = d & 7;
    float s = 0.f;
#pragma unroll 16
    for (int dd = 0; dd < 64; dd++) s = fmaf(qs[bq][dd], ks[bk][dd], s);
    s *= 0.125f;
    float mx = s;
#pragma unroll
    for (int off = 4; off; off >>= 1) mx = fmaxf(mx, __shfl_xor_sync(0xffffffffu, mx, off));
    float p = __expf(s - mx);
    float sum = p;
#pragma unroll
    for (int off = 4; off; off >>= 1) sum += __shfl_xor_sync(0xffffffffu, sum, off);
    ps[bq][bk] = p / sum;
    __syncthreads();
#pragma unroll
    for (int b = 0; b < 8; b++) {
        float a = 0.f;
#pragma unroll
        for (int b2 = 0; b2 < 8; b2++) a = fmaf(ps[b][b2], vs[b2][d], a);
        out[((size_t)(b*NT + t))*ND + h*NDK + d] = __float2half_rn(a);
    }
}

// ---------------- launch ----------------
extern "C" void kernel_launch(void* const* d_in, const int* in_sizes, int n_in,
                              void* d_out, int out_size)
{
    (void)in_sizes; (void)n_in; (void)out_size;
    const float* h    = (const float*)d_in[0];
    const float* lnt  = (const float*)d_in[4];
    const float* lng  = (const float*)d_in[5];
    float* out = (float*)d_out;

    void *normed_, *q_, *k_, *v_, *attn_, *h1_, *wt_, *ctab_, *stab_;
    cudaGetSymbolAddress(&normed_, g_normed);
    cudaGetSymbolAddress(&q_,      g_qb);
    cudaGetSymbolAddress(&k_,      g_kb);
    cudaGetSymbolAddress(&v_,      g_vb);
    cudaGetSymbolAddress(&attn_,   g_attnb);
    cudaGetSymbolAddress(&h1_,     g_h1);
    cudaGetSymbolAddress(&wt_,     g_wt);
    cudaGetSymbolAddress(&ctab_,   g_ctab);
    cudaGetSymbolAddress(&stab_,   g_stab);
    __half* normed = (__half*)normed_;
    __half* q      = (__half*)q_;
    __half* k      = (__half*)k_;
    __half* v      = (__half*)v_;
    __half* attn   = (__half*)attn_;
    float*  h1     = (float*)h1_;
    __half* wt     = (__half*)wt_;
    float*  ctab   = (float*)ctab_;
    float*  stab   = (float*)stab_;

    cudaFuncSetAttribute(gemm_h<0>, cudaFuncAttributeMaxDynamicSharedMemorySize, GSMEM_BYTES);
    cudaFuncSetAttribute(gemm_h<1>, cudaFuncAttributeMaxDynamicSharedMemorySize, GSMEM_BYTES);
    cudaFuncSetAttribute(gemm_h<2>, cudaFuncAttributeMaxDynamicSharedMemorySize, GSMEM_BYTES);
    cudaFuncSetAttribute(flash_h,   cudaFuncAttributeMaxDynamicSharedMemorySize, FL_SMEM_BYTES);

    WPtrs wp;
    for (int i = 0; i < 8; i++) wp.p[i] = (const float*)d_in[6 + i];
    transpose_w<<<dim3(16,16,8), dim3(32,8)>>>(wp, wt);
    rope_table_k<<<8, 128>>>(ctab, stab);

    const size_t WSZ = (size_t)ND*ND;
    dim3 gq(12, NTOK/128);   // fused QKV
    dim3 gr(4,  NTOK/128);   // single GEMM + residual

    // --- time attention ---
    rmsnorm_kernel<<<NTOK, 128>>>(h, lnt, normed);
    gemm_h<1><<<gq, 256, GSMEM_BYTES>>>(normed, wt, nullptr, q, k, v, ctab, stab);
    flash_h<<<dim3(NT/128, NB*NH), 256, FL_SMEM_BYTES>>>(q, k, v, attn);
    gemm_h<0><<<gr, 256, GSMEM_BYTES>>>(attn, wt + 3*WSZ, h, h1, nullptr, nullptr, ctab, stab);

    // --- group attention ---
    rmsnorm_kernel<<<NTOK, 128>>>(h1, lng, normed);
    gemm_h<2><<<gq, 256, GSMEM_BYTES>>>(normed, wt + 4*WSZ, nullptr, q, k, v, ctab, stab);
    group_attn_kernel<<<dim3(NT, NH), 64>>>(q, k, v, attn);
    gemm_h<0><<<gr, 256, GSMEM_BYTES>>>(attn, wt + 7*WSZ, h1, out, nullptr, nullptr, ctab, stab);
}